// round 16
// baseline (speedup 1.0000x reference)
#include <cuda_runtime.h>
#include <cuda_bf16.h>
#include <math.h>
#include <stdint.h>

// ------------------------- device scratch (no allocs allowed) -------------------------
__device__ float g_frames[4224*256];      // windowed STFT frames [b*33+t][n]
__device__ float g_dc_h[256*144];         // DFT cos hi (tf32) [k][n]
__device__ float g_dc_l[256*144];         // DFT cos lo
__device__ float g_ds_h[256*144];         // DFT sin hi
__device__ float g_ds_l[256*144];         // DFT sin lo
__device__ float g_mag [128*33*129];      // [b][t][k]
__device__ int   g_topi[256];
__device__ float g_gw  [256];
__device__ float g_h1  [256*33*256];      // [pair][t][ic]
__device__ float g_l1  [128*64*1024];
__device__ float g_h2p [128*128*256];     // maxpool4 of conv2 output
__device__ float g_ms2 [128*128*16];      // per-tile channel sums of conv2 output
__device__ float g_gate2[128*128];
__device__ float g_h3  [128*256*256];
__device__ float g_gate3[128*256];
__device__ float g_comb[33*128*512];
__device__ float g_ig  [33*128*1024];
__device__ float g_igb [128*1024];
__device__ float g_hbuf1[128*256];
__device__ float g_hb  [128*256];
// transposed weights
__device__ float g_w1t  [8*645*256];
__device__ float g_w2t  [8*768*256];
__device__ float g_wihT [512*1024];
__device__ float g_whhT [256*1024];
__device__ float g_wihbT[512*1024];
__device__ float g_ffn1T[512*256];

__device__ __forceinline__ float sigf(float x) { return 1.0f/(1.0f+expf(-x)); }

__device__ __forceinline__ unsigned f2tf32(float x) {
    unsigned r; asm("cvt.rna.tf32.f32 %0, %1;" : "=r"(r) : "f"(x)); return r;
}
__device__ __forceinline__ void mma_tf32(float* d, const unsigned* a, const unsigned* b) {
    asm volatile(
      "mma.sync.aligned.m16n8k8.row.col.f32.tf32.tf32.f32 "
      "{%0,%1,%2,%3},{%4,%5,%6,%7},{%8,%9},{%0,%1,%2,%3};\n"
      : "+f"(d[0]), "+f"(d[1]), "+f"(d[2]), "+f"(d[3])
      : "r"(a[0]), "r"(a[1]), "r"(a[2]), "r"(a[3]), "r"(b[0]), "r"(b[1]));
}

// ------------------------- fused transposes: in[b][r][c] -> out[b][c][r] -------------------------
__global__ void k_trans_all(const float* __restrict__ p0, const float* __restrict__ p1,
                            const float* __restrict__ p4, const float* __restrict__ p5,
                            const float* __restrict__ p6, const float* __restrict__ p7) {
    int job = blockIdx.y;
    const float* in; float* out; int Bn, R, C;
    switch (job) {
        case 0: in = p0; out = g_w1t;   Bn = 8; R = 256;  C = 645; break;
        case 1: in = p1; out = g_w2t;   Bn = 8; R = 256;  C = 768; break;
        case 2: in = p4; out = g_wihT;  Bn = 1; R = 1024; C = 512; break;
        case 3: in = p5; out = g_whhT;  Bn = 1; R = 1024; C = 256; break;
        case 4: in = p6; out = g_wihbT; Bn = 1; R = 1024; C = 512; break;
        default: in = p7; out = g_ffn1T; Bn = 1; R = 256; C = 512; break;
    }
    long total = (long)Bn * R * C;
    long stride = (long)gridDim.x * blockDim.x;
    for (long i = (long)blockIdx.x*blockDim.x + threadIdx.x; i < total; i += stride) {
        long bb = i / ((long)R*C);
        long rem = i - bb*(long)R*C;
        int r = (int)(rem / C);
        int c = (int)(rem - (long)r*C);
        out[(bb*C + c)*R + r] = in[i];
    }
}

// ------------------------- windowed frame builder (reflect pad, hann) -------------------------
__global__ void k_win(const float* __restrict__ xc) {
    int b = blockIdx.x, f = blockIdx.y;
    int tid = threadIdx.x;                       // 256 threads
    const float W = 6.283185307179586f/256.f;
    int p = f*128 + tid;
    int j = p - 128;
    if (j < 0) j = -j;
    else if (j >= 4096) j = 8190 - j;
    float win = 0.5f*(1.f - cosf(W*(float)tid));
    g_frames[((size_t)(b*33 + f))*256 + tid] = xc[(size_t)b*4096 + j] * win;
}

// ------------------------- DFT matrix builder (hi/lo tf32 split, exact-period args) -----------------
__global__ void k_dftmat() {
    int k = blockIdx.x;                          // 0..255
    int n = threadIdx.x;                         // 0..143
    float c = 0.f, s = 0.f;
    if (n < 129) {
        const float W = 6.283185307179586f/256.f;
        float ang = W * (float)((k*n) & 255);
        sincosf(ang, &s, &c);
    }
    unsigned ch = f2tf32(c), sh = f2tf32(s);
    g_dc_h[k*144 + n] = __uint_as_float(ch);
    g_dc_l[k*144 + n] = c - __uint_as_float(ch);
    g_ds_h[k*144 + n] = __uint_as_float(sh);
    g_ds_l[k*144 + n] = s - __uint_as_float(sh);
}

// ------------------------- DFT magnitude via 3xTF32 MMA: [4224x256] @ [256x129] -----------------
__global__ void __launch_bounds__(256) k_dft() {
    __shared__ unsigned Ah[64*20], Al[64*20];          // [row][kk] stride 20
    __shared__ unsigned Bch[16*148], Bcl[16*148];      // [kk][n] stride 148
    __shared__ unsigned Bsh[16*148], Bsl[16*148];
    int m0 = blockIdx.x * 64;
    int tid = threadIdx.x;
    int lane = tid & 31, warp = tid >> 5;
    int gid = lane >> 2, tig = lane & 3;
    int mw = (warp >> 1) * 16;
    int nbase = (warp & 1) * 72;

    float accr[9][4], acci[9][4];
    #pragma unroll
    for (int ni = 0; ni < 9; ni++)
        #pragma unroll
        for (int r = 0; r < 4; r++) { accr[ni][r] = 0.f; acci[ni][r] = 0.f; }

    for (int k0 = 0; k0 < 256; k0 += 16) {
        __syncthreads();
        #pragma unroll
        for (int j = 0; j < 4; j++) {
            int i = tid + j*256;
            int row = i >> 4, kk = i & 15;
            float x = g_frames[(size_t)(m0 + row)*256 + k0 + kk];
            unsigned h = f2tf32(x);
            Ah[row*20 + kk] = h;
            Al[row*20 + kk] = f2tf32(x - __uint_as_float(h));
        }
        #pragma unroll
        for (int j = 0; j < 9; j++) {
            int i = tid + j*256;
            if (i < 16*144) {
                int kk = i / 144, n = i - kk*144;
                size_t gidx = (size_t)(k0 + kk)*144 + n;
                Bch[kk*148 + n] = __float_as_uint(g_dc_h[gidx]);
                Bcl[kk*148 + n] = f2tf32(g_dc_l[gidx]);
                Bsh[kk*148 + n] = __float_as_uint(g_ds_h[gidx]);
                Bsl[kk*148 + n] = f2tf32(g_ds_l[gidx]);
            }
        }
        __syncthreads();
        #pragma unroll
        for (int ks = 0; ks < 2; ks++) {
            int kk0 = ks*8;
            unsigned ah[4], al[4];
            ah[0] = Ah[(mw+gid  )*20 + kk0 + tig];
            ah[1] = Ah[(mw+gid+8)*20 + kk0 + tig];
            ah[2] = Ah[(mw+gid  )*20 + kk0 + tig + 4];
            ah[3] = Ah[(mw+gid+8)*20 + kk0 + tig + 4];
            al[0] = Al[(mw+gid  )*20 + kk0 + tig];
            al[1] = Al[(mw+gid+8)*20 + kk0 + tig];
            al[2] = Al[(mw+gid  )*20 + kk0 + tig + 4];
            al[3] = Al[(mw+gid+8)*20 + kk0 + tig + 4];
            #pragma unroll
            for (int ni = 0; ni < 9; ni++) {
                int n = nbase + ni*8 + gid;
                unsigned bh[2], bl[2];
                bh[0] = Bch[(kk0+tig  )*148 + n];
                bh[1] = Bch[(kk0+tig+4)*148 + n];
                bl[0] = Bcl[(kk0+tig  )*148 + n];
                bl[1] = Bcl[(kk0+tig+4)*148 + n];
                mma_tf32(accr[ni], ah, bl);
                mma_tf32(accr[ni], al, bh);
                mma_tf32(accr[ni], ah, bh);
                bh[0] = Bsh[(kk0+tig  )*148 + n];
                bh[1] = Bsh[(kk0+tig+4)*148 + n];
                bl[0] = Bsl[(kk0+tig  )*148 + n];
                bl[1] = Bsl[(kk0+tig+4)*148 + n];
                mma_tf32(acci[ni], ah, bl);
                mma_tf32(acci[ni], al, bh);
                mma_tf32(acci[ni], ah, bh);
            }
        }
    }

    int r0 = m0 + mw + gid, r1 = r0 + 8;
    #pragma unroll
    for (int ni = 0; ni < 9; ni++) {
        int n = nbase + ni*8 + tig*2;
        if (n < 129) {
            g_mag[(size_t)r0*129 + n] = sqrtf(accr[ni][0]*accr[ni][0] + acci[ni][0]*acci[ni][0]);
            g_mag[(size_t)r1*129 + n] = sqrtf(accr[ni][2]*accr[ni][2] + acci[ni][2]*acci[ni][2]);
        }
        if (n + 1 < 129) {
            g_mag[(size_t)r0*129 + n + 1] = sqrtf(accr[ni][1]*accr[ni][1] + acci[ni][1]*acci[ni][1]);
            g_mag[(size_t)r1*129 + n + 1] = sqrtf(accr[ni][3]*accr[ni][3] + acci[ni][3]*acci[ni][3]);
        }
    }
}

// ------------------------- gating MLP + top-2 softmax -------------------------
__global__ void k_gate(const float* __restrict__ w1, const float* __restrict__ b1,
                       const float* __restrict__ w2, const float* __restrict__ b2) {
    int b = blockIdx.x;
    __shared__ float pooled[129];
    __shared__ float hid[128];
    __shared__ float lg[8];
    int tid = threadIdx.x;                       // 160 threads
    if (tid < 129) {
        float s = 0.f;
        const float* mp = g_mag + (size_t)b*33*129 + tid;
        for (int f = 0; f < 33; f++) s += mp[f*129];
        pooled[tid] = s * (1.f/33.f);
    }
    __syncthreads();
    if (tid < 128) {
        float s = b1[tid];
        const float* wr = w1 + tid*129;
        for (int i = 0; i < 129; i++) s += pooled[i]*wr[i];
        hid[tid] = fmaxf(s, 0.f);
    }
    __syncthreads();
    if (tid < 8) {
        float s = b2[tid];
        const float* wr = w2 + tid*128;
        for (int j = 0; j < 128; j++) s += hid[j]*wr[j];
        lg[tid] = s;
    }
    __syncthreads();
    if (tid == 0) {
        int i0 = 0; float v0 = lg[0];
        for (int i = 1; i < 8; i++) if (lg[i] > v0) { v0 = lg[i]; i0 = i; }
        int i1 = -1; float v1 = -3.0e38f;
        for (int i = 0; i < 8; i++) if (i != i0 && lg[i] > v1) { v1 = lg[i]; i1 = i; }
        float e = expf(v1 - v0);
        float d = 1.f/(1.f + e);
        g_topi[2*b] = i0; g_topi[2*b+1] = i1;
        g_gw[2*b] = d;    g_gw[2*b+1] = e*d;
    }
}

// ------------------------- expert conv1 (129->256,k5,p2): SIMT fp32, vectorized LDS ----------------
// 512 blocks x 256 thr. Segments t0=0 (writes t 0..16) and t0=16 (writes t 17..32).
__global__ void __launch_bounds__(256) k_exp1(const float* __restrict__ eb1) {
    int pair = blockIdx.x >> 1;
    int half = blockIdx.x & 1;
    int b = pair >> 1;
    int e = g_topi[pair];
    __shared__ float ms[129][40];                // stride 40 -> 16B-aligned rows
    int tid = threadIdx.x;
    for (int i = tid; i < 129*40; i += 256) ((float*)ms)[i] = 0.f;
    __syncthreads();
    for (int i = tid; i < 33*129; i += 256) {
        int t = i/129, ic = i - t*129;
        ms[ic][t+2] = g_mag[(size_t)b*33*129 + i];
    }
    __syncthreads();
    int oc   = half*128 + (tid & 127);
    int tseg = tid >> 7;
    int t0   = tseg * 16;
    float acc[17];
    #pragma unroll
    for (int t = 0; t < 17; t++) acc[t] = 0.f;
    const float* wb = g_w1t + (size_t)e*645*256 + oc;
    for (int ic = 0; ic < 129; ic++) {
        float row[21];
        const float4* rp = (const float4*)&ms[ic][t0];
        #pragma unroll
        for (int j = 0; j < 5; j++) {
            float4 v = rp[j];
            row[4*j] = v.x; row[4*j+1] = v.y; row[4*j+2] = v.z; row[4*j+3] = v.w;
        }
        row[20] = ms[ic][t0 + 20];
        #pragma unroll
        for (int dk = 0; dk < 5; dk++) {
            float w = __ldg(wb + (ic*5 + dk)*256);
            #pragma unroll
            for (int t = 0; t < 17; t++) acc[t] += w * row[t+dk];
        }
    }
    float bias = eb1[e*256 + oc];
    float* op = g_h1 + (size_t)pair*33*256 + oc;
    #pragma unroll
    for (int t = 0; t < 17; t++)
        if (tseg == 0 || t > 0)                  // t=16 written once (by seg0)
            op[(t0 + t)*256] = fmaxf(acc[t] + bias, 0.f);
}

// ------------------------- expert conv2 (256->256,k3,p1): per-batch, both experts, writes comb ------
// 256 blocks = (b, oc-half) x 256 thr. Both h1 tiles staged; gate-weighted sum -> g_comb freq half.
#define EXP2_SMEM (2*256*40*4)
__global__ void __launch_bounds__(256) k_exp2(const float* __restrict__ eb2) {
    extern __shared__ float hs[];                // [2][256][40]
    int b = blockIdx.x >> 1;
    int half = blockIdx.x & 1;
    int tid = threadIdx.x;
    for (int i = tid; i < 2*256*40; i += 256) hs[i] = 0.f;
    __syncthreads();
    #pragma unroll
    for (int k2 = 0; k2 < 2; k2++) {
        const float* src = g_h1 + (size_t)(b*2 + k2)*33*256;
        float* dst = hs + k2*10240;
        for (int i = tid; i < 33*256; i += 256) {
            int t = i >> 8, ic = i & 255;
            dst[ic*40 + t + 1] = src[i];
        }
    }
    __syncthreads();
    int oc   = half*128 + (tid & 127);
    int tseg = tid >> 7;
    int t0   = tseg * 16;
    float res[17];
    #pragma unroll
    for (int t = 0; t < 17; t++) res[t] = 0.f;
    #pragma unroll
    for (int k2 = 0; k2 < 2; k2++) {
        int e = g_topi[b*2 + k2];
        float gwk = g_gw[b*2 + k2];
        const float* wb = g_w2t + (size_t)e*768*256 + oc;
        const float* hsk = hs + k2*10240;
        float acc[17];
        #pragma unroll
        for (int t = 0; t < 17; t++) acc[t] = 0.f;
        for (int ic = 0; ic < 256; ic++) {
            float row[20];
            const float4* rp = (const float4*)&hsk[ic*40 + t0];
            #pragma unroll
            for (int j = 0; j < 5; j++) {
                float4 v = rp[j];
                row[4*j] = v.x; row[4*j+1] = v.y; row[4*j+2] = v.z; row[4*j+3] = v.w;
            }
            #pragma unroll
            for (int dk = 0; dk < 3; dk++) {
                float w = __ldg(wb + (ic*3 + dk)*256);
                #pragma unroll
                for (int t = 0; t < 17; t++) acc[t] += w * row[t+dk];
            }
        }
        float bias = eb2[e*256 + oc];
        #pragma unroll
        for (int t = 0; t < 17; t++) res[t] += gwk * fmaxf(acc[t] + bias, 0.f);
    }
    #pragma unroll
    for (int t = 0; t < 17; t++)
        if (tseg == 0 || t > 0)
            g_comb[((size_t)(t0 + t)*128 + b)*512 + oc] = res[t];
}

// ------------------------- line conv1 (1->64,k7,p3) fused maxpool4 -------------------------
__global__ void __launch_bounds__(1024) k_lconv1(const float* __restrict__ xn,
                                                 const float* __restrict__ lw1,
                                                 const float* __restrict__ lb1) {
    int b = blockIdx.x;
    __shared__ float xs[4102];
    __shared__ float ws[448];
    __shared__ float bs[64];
    int tid = threadIdx.x;
    for (int i = tid; i < 4102; i += 1024) {
        int p = i - 3;
        xs[i] = (p >= 0 && p < 4096) ? xn[(size_t)b*4096 + p] : 0.f;
    }
    if (tid < 448) ws[tid] = lw1[tid];
    if (tid < 64)  bs[tid] = lb1[tid];
    __syncthreads();
    int p = tid;
    float xv[10];
    #pragma unroll
    for (int i = 0; i < 10; i++) xv[i] = xs[4*p + i];
    for (int c = 0; c < 64; c++) {
        const float* w = ws + c*7;
        float mx = -3.0e38f;
        #pragma unroll
        for (int q = 0; q < 4; q++) {
            float s = 0.f;
            #pragma unroll
            for (int k = 0; k < 7; k++) s += xv[q+k]*w[k];
            mx = fmaxf(mx, s);
        }
        g_l1[((size_t)b*64 + c)*1024 + p] = fmaxf(mx + bs[c], 0.f);
    }
}

// ------------------------- line conv2 (64->128,k5,p2) tf32 mma, FUSED relu+maxpool4+channel sums -----
#define LC2_SMEM ((64*133 + 128*44) * 4)
__global__ void __launch_bounds__(256) k_lconv2(const float* __restrict__ lw2,
                                                const float* __restrict__ lb2) {
    extern __shared__ unsigned smu[];
    unsigned* xs = smu;                 // stride 133
    unsigned* As = smu + 64*133;        // stride 44
    int b = blockIdx.x, t0 = blockIdx.y*128;
    int tid = threadIdx.x;
    int lane = tid & 31, warp = tid >> 5;
    int gid = lane >> 2, tig = lane & 3;
    int m_base = (warp >> 1) * 32;
    int n_base = (warp & 1) * 64;

    for (int i = tid; i < 64*132; i += 256) {
        int ic = i / 132, u = i - ic*132;
        int t = t0 + u - 2;
        float v = (t >= 0 && t < 1024) ? g_l1[((size_t)b*64 + ic)*1024 + t] : 0.f;
        xs[ic*133 + u] = f2tf32(v);
    }

    float acc[2][8][4];
    #pragma unroll
    for (int mi = 0; mi < 2; mi++)
        #pragma unroll
        for (int ni = 0; ni < 8; ni++)
            #pragma unroll
            for (int r = 0; r < 4; r++) acc[mi][ni][r] = 0.f;

    for (int ic0 = 0; ic0 < 64; ic0 += 8) {
        __syncthreads();
        for (int i = tid; i < 128*40; i += 256) {
            int oc = i / 40, kk = i - oc*40;
            As[oc*44 + kk] = f2tf32(lw2[oc*320 + ic0*5 + kk]);
        }
        __syncthreads();
        #pragma unroll
        for (int ks = 0; ks < 5; ks++) {
            int kk0 = ks*8;
            unsigned a[2][4];
            #pragma unroll
            for (int mi = 0; mi < 2; mi++) {
                int row = m_base + mi*16;
                a[mi][0] = As[(row+gid  )*44 + kk0 + tig];
                a[mi][1] = As[(row+gid+8)*44 + kk0 + tig];
                a[mi][2] = As[(row+gid  )*44 + kk0 + tig + 4];
                a[mi][3] = As[(row+gid+8)*44 + kk0 + tig + 4];
            }
            int kb0 = kk0 + tig, kb1 = kb0 + 4;
            int ica = kb0/5, dka = kb0 - ica*5;
            int icb = kb1/5, dkb = kb1 - icb*5;
            const unsigned* xra = xs + (ic0 + ica)*133 + dka;
            const unsigned* xrb = xs + (ic0 + icb)*133 + dkb;
            #pragma unroll
            for (int ni = 0; ni < 8; ni++) {
                int n = n_base + ni*8 + gid;
                unsigned bfrag[2];
                bfrag[0] = xra[n];
                bfrag[1] = xrb[n];
                mma_tf32(acc[0][ni], a[0], bfrag);
                mma_tf32(acc[1][ni], a[1], bfrag);
            }
        }
    }

    int pbase = blockIdx.y*32 + (n_base >> 2);
    #pragma unroll
    for (int mi = 0; mi < 2; mi++) {
        int oc0 = m_base + mi*16 + gid, oc1 = oc0 + 8;
        float b0v = lb2[oc0], b1v = lb2[oc1];
        float s0 = 0.f, s1 = 0.f;
        #pragma unroll
        for (int ni = 0; ni < 8; ni++) {
            float v0 = fmaxf(acc[mi][ni][0] + b0v, 0.f);
            float v1 = fmaxf(acc[mi][ni][1] + b0v, 0.f);
            float v2 = fmaxf(acc[mi][ni][2] + b1v, 0.f);
            float v3 = fmaxf(acc[mi][ni][3] + b1v, 0.f);
            s0 += v0 + v1;
            s1 += v2 + v3;
            float m0 = fmaxf(v0, v1), m1 = fmaxf(v2, v3);
            m0 = fmaxf(m0, __shfl_xor_sync(0xffffffffu, m0, 1));
            m1 = fmaxf(m1, __shfl_xor_sync(0xffffffffu, m1, 1));
            if ((tig & 1) == 0) {
                int p = pbase + ni*2 + (tig >> 1);
                g_h2p[((size_t)b*128 + oc0)*256 + p] = m0;
                g_h2p[((size_t)b*128 + oc1)*256 + p] = m1;
            }
        }
        s0 += __shfl_xor_sync(0xffffffffu, s0, 1);
        s0 += __shfl_xor_sync(0xffffffffu, s0, 2);
        s1 += __shfl_xor_sync(0xffffffffu, s1, 1);
        s1 += __shfl_xor_sync(0xffffffffu, s1, 2);
        if (tig == 0) {
            int seg = blockIdx.y*2 + (warp & 1);
            g_ms2[((size_t)b*128 + oc0)*16 + seg] = s0;
            g_ms2[((size_t)b*128 + oc1)*16 + seg] = s1;
        }
    }
}

// ------------------------- SE block 2 (128 ch, hidden 32) — reduces 16 partials -------------------------
__global__ void k_se2(const float* __restrict__ w1, const float* __restrict__ w2) {
    int b = blockIdx.x;
    __shared__ float mean[128];
    __shared__ float hid[32];
    int tid = threadIdx.x;                       // 128 threads
    {
        const float* mp = g_ms2 + ((size_t)b*128 + tid)*16;
        float s = 0.f;
        #pragma unroll
        for (int i = 0; i < 16; i++) s += mp[i];
        mean[tid] = s * (1.f/1024.f);
    }
    __syncthreads();
    if (tid < 32) {
        float s = 0.f;
        const float* wr = w1 + tid*128;
        for (int c = 0; c < 128; c++) s += mean[c]*wr[c];
        hid[tid] = fmaxf(s, 0.f);
    }
    __syncthreads();
    {
        float s = 0.f;
        const float* wr = w2 + tid*32;
        for (int k = 0; k < 32; k++) s += hid[k]*wr[k];
        g_gate2[b*128 + tid] = sigf(s);
    }
}

// ------------------------- line conv3 (128->256,k3,p1) via tf32 mma — reads pooled g_h2p ------------
#define LC3_SMEM ((128*67 + 256*28) * 4)
__global__ void __launch_bounds__(256) k_lconv3(const float* __restrict__ lw3,
                                                const float* __restrict__ lb3) {
    extern __shared__ unsigned smu[];
    unsigned* xs = smu;                 // stride 67
    unsigned* As = smu + 128*67;        // stride 28
    int b = blockIdx.x, t0 = blockIdx.y*64;
    int tid = threadIdx.x;
    int lane = tid & 31, warp = tid >> 5;
    int gid = lane >> 2, tig = lane & 3;
    int m_base = (warp >> 1) * 64;
    int n_base = (warp & 1) * 32;

    for (int i = tid; i < 128*66; i += 256) {
        int ic = i / 66, u = i - ic*66;
        int t = t0 + u - 1;
        float v = 0.f;
        if (t >= 0 && t < 256)
            v = g_h2p[((size_t)b*128 + ic)*256 + t] * g_gate2[b*128 + ic];
        xs[ic*67 + u] = f2tf32(v);
    }

    float acc[4][4][4];
    #pragma unroll
    for (int mi = 0; mi < 4; mi++)
        #pragma unroll
        for (int ni = 0; ni < 4; ni++)
            #pragma unroll
            for (int r = 0; r < 4; r++) acc[mi][ni][r] = 0.f;

    for (int ic0 = 0; ic0 < 128; ic0 += 8) {
        __syncthreads();
        for (int i = tid; i < 256*24; i += 256) {
            int oc = i / 24, kk = i - oc*24;
            As[oc*28 + kk] = f2tf32(lw3[oc*384 + ic0*3 + kk]);
        }
        __syncthreads();
        #pragma unroll
        for (int ks = 0; ks < 3; ks++) {
            int kk0 = ks*8;
            unsigned a[4][4];
            #pragma unroll
            for (int mi = 0; mi < 4; mi++) {
                int row = m_base + mi*16;
                a[mi][0] = As[(row+gid  )*28 + kk0 + tig];
                a[mi][1] = As[(row+gid+8)*28 + kk0 + tig];
                a[mi][2] = As[(row+gid  )*28 + kk0 + tig + 4];
                a[mi][3] = As[(row+gid+8)*28 + kk0 + tig + 4];
            }
            int kb0 = kk0 + tig, kb1 = kb0 + 4;
            int ica = kb0/3, dka = kb0 - ica*3;
            int icb = kb1/3, dkb = kb1 - icb*3;
            const unsigned* xra = xs + (ic0 + ica)*67 + dka;
            const unsigned* xrb = xs + (ic0 + icb)*67 + dkb;
            #pragma unroll
            for (int ni = 0; ni < 4; ni++) {
                int n = n_base + ni*8 + gid;
                unsigned bfrag[2];
                bfrag[0] = xra[n];
                bfrag[1] = xrb[n];
                #pragma unroll
                for (int mi = 0; mi < 4; mi++)
                    mma_tf32(acc[mi][ni], a[mi], bfrag);
            }
        }
    }

    #pragma unroll
    for (int mi = 0; mi < 4; mi++) {
        int oc0 = m_base + mi*16 + gid, oc1 = oc0 + 8;
        float b0v = lb3[oc0], b1v = lb3[oc1];
        float* p0b = g_h3 + ((size_t)b*256 + oc0)*256 + t0;
        float* p1b = g_h3 + ((size_t)b*256 + oc1)*256 + t0;
        #pragma unroll
        for (int ni = 0; ni < 4; ni++) {
            int t = n_base + ni*8 + tig*2;
            p0b[t  ] = fmaxf(acc[mi][ni][0] + b0v, 0.f);
            p0b[t+1] = fmaxf(acc[mi][ni][1] + b0v, 0.f);
            p1b[t  ] = fmaxf(acc[mi][ni][2] + b1v, 0.f);
            p1b[t+1] = fmaxf(acc[mi][ni][3] + b1v, 0.f);
        }
    }
}

// ------------------------- SE block 3 (256 ch, hidden 64) -------------------------
__global__ void k_se3(const float* __restrict__ w1, const float* __restrict__ w2) {
    int b = blockIdx.x;
    __shared__ float mean[256];
    __shared__ float hid[64];
    int tid = threadIdx.x;
    {
        const float4* p = (const float4*)(g_h3 + ((size_t)b*256 + tid)*256);
        float s = 0.f;
        for (int i = 0; i < 64; i++) { float4 v = p[i]; s += v.x+v.y+v.z+v.w; }
        mean[tid] = s * (1.f/256.f);
    }
    __syncthreads();
    if (tid < 64) {
        float s = 0.f;
        const float* wr = w1 + tid*256;
        for (int c = 0; c < 256; c++) s += mean[c]*wr[c];
        hid[tid] = fmaxf(s, 0.f);
    }
    __syncthreads();
    {
        float s = 0.f;
        const float* wr = w2 + tid*64;
        for (int k = 0; k < 64; k++) s += hid[k]*wr[k];
        g_gate3[b*256 + tid] = sigf(s);
    }
}

// ------------------------- build comb line half: comb[t][b][256+cc] -------------------------
__global__ void k_comb() {
    const float scale = 64.f/33.f;
    int total = 33*128*256;
    for (int idx = blockIdx.x*blockDim.x + threadIdx.x; idx < total;
         idx += gridDim.x*blockDim.x) {
        int cc = idx & 255;
        int rem = idx >> 8;
        int b = rem & 127;
        int t = rem >> 7;
        float co = ((float)t + 0.5f)*scale - 0.5f;
        co = fminf(fmaxf(co, 0.f), 63.f);
        int lo = (int)floorf(co);
        int hi = min(lo + 1, 63);
        float w = co - (float)lo;
        const float* hp = g_h3 + ((size_t)b*256 + cc)*256;
        float g = g_gate3[b*256 + cc];
        const float* pl = hp + 4*lo;
        float vl = fmaxf(fmaxf(pl[0], pl[1]), fmaxf(pl[2], pl[3]));
        const float* ph = hp + 4*hi;
        float vh = fmaxf(fmaxf(ph[0], ph[1]), fmaxf(ph[2], ph[3]));
        g_comb[((size_t)t*128 + b)*512 + 256 + cc] = g * (vl*(1.f - w) + vh*w);
    }
}

// ------------------------- GEMM via 3xTF32 mma (error-compensated, ~fp32 accuracy) ------------------
#define GEMM_SMEM ((128*36 + 32*132) * 8)
__global__ void __launch_bounds__(256) k_gemm(int mode,
        const float* __restrict__ bi1, const float* __restrict__ bi2) {
    extern __shared__ unsigned smu[];
    unsigned* Ash = smu;                         // [128][36] hi
    unsigned* Asl = smu + 128*36;                // [128][36] lo
    unsigned* Bsh = smu + 2*128*36;              // [32][132] hi
    unsigned* Bsl = smu + 2*128*36 + 32*132;     // [32][132] lo
    const float* A; const float* Bt; float* C;
    if (mode == 0) { A = g_comb;              Bt = g_wihT;  C = g_ig;  }
    else           { A = g_comb + 32*128*512; Bt = g_wihbT; C = g_igb; }
    int m0 = blockIdx.x*128, n0 = blockIdx.y*128;
    int tid = threadIdx.x;
    int lane = tid & 31, warp = tid >> 5;
    int gid = lane >> 2, tig = lane & 3;
    int m_base = (warp >> 1) * 32;
    int n_base = (warp & 1) * 64;

    float acc[2][8][4];
    #pragma unroll
    for (int mi = 0; mi < 2; mi++)
        #pragma unroll
        for (int ni = 0; ni < 8; ni++)
            #pragma unroll
            for (int r = 0; r < 4; r++) acc[mi][ni][r] = 0.f;

    for (int k0 = 0; k0 < 512; k0 += 32) {
        __syncthreads();
        #pragma unroll
        for (int j = 0; j < 16; j++) {
            int i = tid + j*256;
            int row = i >> 5, kk = i & 31;
            float x = A[(size_t)(m0+row)*512 + k0 + kk];
            unsigned h = f2tf32(x);
            Ash[row*36 + kk] = h;
            Asl[row*36 + kk] = f2tf32(x - __uint_as_float(h));
        }
        #pragma unroll
        for (int j = 0; j < 16; j++) {
            int i = tid + j*256;
            int kk = i >> 7, n = i & 127;
            float x = Bt[(size_t)(k0+kk)*1024 + n0 + n];
            unsigned h = f2tf32(x);
            Bsh[kk*132 + n] = h;
            Bsl[kk*132 + n] = f2tf32(x - __uint_as_float(h));
        }
        __syncthreads();
        #pragma unroll
        for (int ks = 0; ks < 4; ks++) {
            int kk0 = ks*8;
            unsigned ah[2][4], al[2][4];
            #pragma unroll
            for (int mi = 0; mi < 2; mi++) {
                int row = m_base + mi*16;
                ah[mi][0] = Ash[(row+gid  )*36 + kk0 + tig];
                ah[mi][1] = Ash[(row+gid+8)*36 + kk0 + tig];
                ah[mi][2] = Ash[(row+gid  )*36 + kk0 + tig + 4];
                ah[mi][3] = Ash[(row+gid+8)*36 + kk0 + tig + 4];
                al[mi][0] = Asl[(row+gid  )*36 + kk0 + tig];
                al[mi][1] = Asl[(row+gid+8)*36 + kk0 + tig];
                al[mi][2] = Asl[(row+gid  )*36 + kk0 + tig + 4];
                al[mi][3] = Asl[(row+gid+8)*36 + kk0 + tig + 4];
            }
            #pragma unroll
            for (int ni = 0; ni < 8; ni++) {
                int n = n_base + ni*8 + gid;
                unsigned bh[2], bl[2];
                bh[0] = Bsh[(kk0+tig  )*132 + n];
                bh[1] = Bsh[(kk0+tig+4)*132 + n];
                bl[0] = Bsl[(kk0+tig  )*132 + n];
                bl[1] = Bsl[(kk0+tig+4)*132 + n];
                mma_tf32(acc[0][ni], ah[0], bl);
                mma_tf32(acc[0][ni], al[0], bh);
                mma_tf32(acc[0][ni], ah[0], bh);
                mma_tf32(acc[1][ni], ah[1], bl);
                mma_tf32(acc[1][ni], al[1], bh);
                mma_tf32(acc[1][ni], ah[1], bh);
            }
        }
    }

    #pragma unroll
    for (int mi = 0; mi < 2; mi++) {
        int m0r = m0 + m_base + mi*16 + gid;
        int m1r = m0r + 8;
        #pragma unroll
        for (int ni = 0; ni < 8; ni++) {
            int n = n0 + n_base + ni*8 + tig*2;
            float bb0 = bi1[n] + bi2[n], bb1 = bi1[n+1] + bi2[n+1];
            C[(size_t)m0r*1024 + n    ] = acc[mi][ni][0] + bb0;
            C[(size_t)m0r*1024 + n + 1] = acc[mi][ni][1] + bb1;
            C[(size_t)m1r*1024 + n    ] = acc[mi][ni][2] + bb0;
            C[(size_t)m1r*1024 + n + 1] = acc[mi][ni][3] + bb1;
        }
    }
}

// ------------------------- persistent cluster LSTM (all 33 steps, one launch) -------------------------
#define LSTM_SMEM ((256*128 + 2*8*256 + 8*8*128) * 4)
__global__ void __cluster_dims__(8,1,1) __launch_bounds__(256, 1) k_lstm() {
    extern __shared__ float sm[];
    float* ws   = sm;
    float* hbuf = sm + 256*128;
    float* red  = hbuf + 2*8*256;
    int tid = threadIdx.x;
    unsigned rank;
    asm("mov.u32 %0, %%cluster_ctarank;" : "=r"(rank));
    int bg = blockIdx.x >> 3;
    int j0 = (int)rank * 32;

    for (int i = tid; i < 256*128; i += 256) {
        int k = i >> 7; int col = i & 127;
        int g = col >> 5; int jj = col & 31;
        ws[i] = g_whhT[k*1024 + g*256 + j0 + jj];
    }
    for (int i = tid; i < 8*256; i += 256) hbuf[i] = 0.f;
    __syncthreads();
    asm volatile("barrier.cluster.arrive.aligned;" ::: "memory");
    asm volatile("barrier.cluster.wait.aligned;" ::: "memory");

    int ks = tid >> 5, jj = tid & 31;
    int rb = tid >> 5, rjj = tid & 31;
    float c_reg = 0.f;
    float hval  = 0.f;

    for (int t = 0; t < 33; t++) {
        const float* hp = hbuf + (t & 1) * 2048;
        float acc[8][4];
        #pragma unroll
        for (int b = 0; b < 8; b++)
            #pragma unroll
            for (int g = 0; g < 4; g++) acc[b][g] = 0.f;
        int kbase = ks*32;
        #pragma unroll 4
        for (int kk = 0; kk < 32; kk++) {
            int k = kbase + kk;
            float w0 = ws[k*128 + jj];
            float w1 = ws[k*128 + 32 + jj];
            float w2 = ws[k*128 + 64 + jj];
            float w3 = ws[k*128 + 96 + jj];
            #pragma unroll
            for (int b = 0; b < 8; b++) {
                float hk = hp[b*256 + k];
                acc[b][0] += hk*w0; acc[b][1] += hk*w1;
                acc[b][2] += hk*w2; acc[b][3] += hk*w3;
            }
        }
        #pragma unroll
        for (int b = 0; b < 8; b++)
            #pragma unroll
            for (int g = 0; g < 4; g++)
                red[(ks*8 + b)*128 + g*32 + jj] = acc[b][g];
        __syncthreads();

        float gi = 0.f, gf = 0.f, gg = 0.f, go = 0.f;
        #pragma unroll
        for (int q = 0; q < 8; q++) {
            const float* rp = red + (q*8 + rb)*128;
            gi += rp[rjj]; gf += rp[32+rjj]; gg += rp[64+rjj]; go += rp[96+rjj];
        }
        const float* igp = g_ig + ((size_t)t*128 + bg*8 + rb)*1024 + j0 + rjj;
        gi += igp[0]; gf += igp[256]; gg += igp[512]; go += igp[768];
        c_reg = sigf(gf)*c_reg + sigf(gi)*tanhf(gg);
        hval  = sigf(go)*tanhf(c_reg);

        uint32_t dst_local = (uint32_t)__cvta_generic_to_shared(
            hbuf + ((t+1)&1)*2048 + rb*256 + j0 + rjj);
        #pragma unroll
        for (int r = 0; r < 8; r++) {
            uint32_t remote;
            asm volatile("mapa.shared::cluster.u32 %0, %1, %2;"
                         : "=r"(remote) : "r"(dst_local), "r"(r));
            asm volatile("st.shared::cluster.f32 [%0], %1;"
                         :: "r"(remote), "f"(hval) : "memory");
        }
        asm volatile("barrier.cluster.arrive.aligned;" ::: "memory");
        asm volatile("barrier.cluster.wait.aligned;" ::: "memory");
    }
    g_hbuf1[(bg*8 + rb)*256 + j0 + rjj] = hval;
}

// ------------------------- backward LSTM: single step from zero state -------------------------
__global__ void k_bw() {
    int idx = blockIdx.x*blockDim.x + threadIdx.x;
    if (idx >= 128*256) return;
    int b = idx >> 8, j = idx & 255;
    const float* gp = g_igb + b*1024;
    float gi = gp[j], gg = gp[512+j], go = gp[768+j];
    float c = sigf(gi)*tanhf(gg);
    g_hb[idx] = sigf(go)*tanhf(c);
}

// ------------------------- final FFN -------------------------
__global__ void k_ffn(const float* __restrict__ b1v, const float* __restrict__ w2,
                      const float* __restrict__ b2v, float* __restrict__ out) {
    int b = blockIdx.x;
    __shared__ float last[512];
    __shared__ float red[256];
    int tid = threadIdx.x;
    last[tid]       = g_hbuf1[b*256 + tid];
    last[256 + tid] = g_hb[b*256 + tid];
    __syncthreads();
    float s = b1v[tid];
    for (int k = 0; k < 512; k++) s += last[k]*g_ffn1T[k*256 + tid];
    s = fmaxf(s, 0.f);
    red[tid] = s * w2[tid];
    __syncthreads();
    for (int off = 128; off > 0; off >>= 1) {
        if (tid < off) red[tid] += red[tid + off];
        __syncthreads();
    }
    if (tid == 0) out[b] = red[0] + b2v[0];
}

// ------------------------- launch -------------------------
extern "C" void kernel_launch(void* const* d_in, const int* in_sizes, int n_in,
                              void* d_out, int out_size) {
    const float* x_continuum  = (const float*)d_in[0];
    const float* x_normalized = (const float*)d_in[1];
    const float* gate_w1 = (const float*)d_in[2];
    const float* gate_b1 = (const float*)d_in[3];
    const float* gate_w2 = (const float*)d_in[4];
    const float* gate_b2 = (const float*)d_in[5];
    const float* exp_w1  = (const float*)d_in[6];
    const float* exp_b1  = (const float*)d_in[7];
    const float* exp_w2  = (const float*)d_in[8];
    const float* exp_b2  = (const float*)d_in[9];
    const float* lw1 = (const float*)d_in[10];
    const float* lb1 = (const float*)d_in[11];
    const float* lw2 = (const float*)d_in[12];
    const float* lb2 = (const float*)d_in[13];
    const float* se2_w1 = (const float*)d_in[14];
    const float* se2_w2 = (const float*)d_in[15];
    const float* lw3 = (const float*)d_in[16];
    const float* lb3 = (const float*)d_in[17];
    const float* se3_w1 = (const float*)d_in[18];
    const float* se3_w2 = (const float*)d_in[19];
    const float* wih_f = (const float*)d_in[20];
    const float* whh_f = (const float*)d_in[21];
    const float* bih_f = (const float*)d_in[22];
    const float* bhh_f = (const float*)d_in[23];
    const float* wih_b = (const float*)d_in[24];
    // d_in[25] = whh_b: unused (backward LSTM only contributes one step from h=0)
    const float* bih_b = (const float*)d_in[26];
    const float* bhh_b = (const float*)d_in[27];
    const float* ffn_w1 = (const float*)d_in[28];
    const float* ffn_b1 = (const float*)d_in[29];
    const float* ffn_w2 = (const float*)d_in[30];
    const float* ffn_b2 = (const float*)d_in[31];
    float* out = (float*)d_out;

    // Create streams/events ONCE (first call = correctness run, pre-capture baseline).
    static bool s_init = false;
    static cudaStream_t s1, s2;
    static cudaEvent_t eF, eT, eJ1, eC, eJ3, eEnd;
    if (!s_init) {
        cudaStreamCreateWithFlags(&s1, cudaStreamNonBlocking);
        cudaStreamCreateWithFlags(&s2, cudaStreamNonBlocking);
        cudaEventCreateWithFlags(&eF,   cudaEventDisableTiming);
        cudaEventCreateWithFlags(&eT,   cudaEventDisableTiming);
        cudaEventCreateWithFlags(&eJ1,  cudaEventDisableTiming);
        cudaEventCreateWithFlags(&eC,   cudaEventDisableTiming);
        cudaEventCreateWithFlags(&eJ3,  cudaEventDisableTiming);
        cudaEventCreateWithFlags(&eEnd, cudaEventDisableTiming);
        cudaFuncSetAttribute(k_lstm,   cudaFuncAttributeMaxDynamicSharedMemorySize, LSTM_SMEM);
        cudaFuncSetAttribute(k_lconv2, cudaFuncAttributeMaxDynamicSharedMemorySize, LC2_SMEM);
        cudaFuncSetAttribute(k_lconv3, cudaFuncAttributeMaxDynamicSharedMemorySize, LC3_SMEM);
        cudaFuncSetAttribute(k_gemm,   cudaFuncAttributeMaxDynamicSharedMemorySize, GEMM_SMEM);
        cudaFuncSetAttribute(k_exp2,   cudaFuncAttributeMaxDynamicSharedMemorySize, EXP2_SMEM);
        s_init = true;
    }

    // fork from capture stream
    cudaEventRecord(eF, 0);
    cudaStreamWaitEvent(s1, eF, 0);
    cudaStreamWaitEvent(s2, eF, 0);

    // record order puts k_lconv2 4th so ncu (-s 5 -c 1 behavior observed = 4th kernel) profiles it
    k_trans_all<<<dim3(768, 6), 256, 0, s2>>>(exp_w1, exp_w2, wih_f, whh_f, wih_b, ffn_w1);   // 1
    cudaEventRecord(eT, s2);
    k_lconv1<<<128, 1024, 0, s2>>>(x_normalized, lw1, lb1);                                    // 2
    k_dftmat<<<256, 144, 0, s1>>>();                                                           // 3
    k_lconv2<<<dim3(128, 8), 256, LC2_SMEM, s2>>>(lw2, lb2);                                   // 4
    k_win<<<dim3(128, 33), 256, 0, s1>>>(x_continuum);                                         // 5
    k_dft<<<66, 256, 0, s1>>>();                                                               // 6
    k_gate<<<128, 160, 0, s1>>>(gate_w1, gate_b1, gate_w2, gate_b2);                           // 7
    k_se2<<<128, 128, 0, s2>>>(se2_w1, se2_w2);
    k_lconv3<<<dim3(128, 4), 256, LC3_SMEM, s2>>>(lw3, lb3);
    k_se3<<<128, 256, 0, s2>>>(se3_w1, se3_w2);

    cudaStreamWaitEvent(s1, eT, 0);          // experts need transposed weights
    k_exp1<<<512, 256, 0, s1>>>(exp_b1);
    k_exp2<<<256, 256, EXP2_SMEM, s1>>>(exp_b2);   // writes comb freq half directly
    cudaEventRecord(eJ1, s1);

    // s2: line interp half of comb
    cudaStreamWaitEvent(s2, eJ1, 0);
    k_comb<<<2048, 512, 0, s2>>>();
    cudaEventRecord(eC, s2);

    // s1: backward-LSTM path overlaps forward GEMM
    cudaStreamWaitEvent(s1, eC, 0);
    k_gemm<<<dim3(1, 8), 256, GEMM_SMEM, s1>>>(1, bih_b, bhh_b);
    k_bw<<<128, 256, 0, s1>>>();
    cudaEventRecord(eJ3, s1);

    // s2: forward input projections + persistent LSTM + FFN
    k_gemm<<<dim3(33, 8), 256, GEMM_SMEM, s2>>>(0, bih_f, bhh_f);
    k_lstm<<<128, 256, LSTM_SMEM, s2>>>();
    cudaStreamWaitEvent(s2, eJ3, 0);
    k_ffn<<<128, 256, 0, s2>>>(ffn_b1, ffn_w2, ffn_b2, out);
    cudaEventRecord(eEnd, s2);

    // join back to capture stream
    cudaStreamWaitEvent(0, eEnd, 0);
}

// round 17
// speedup vs baseline: 1.1503x; 1.1503x over previous
#include <cuda_runtime.h>
#include <cuda_bf16.h>
#include <math.h>
#include <stdint.h>

// ------------------------- device scratch (no allocs allowed) -------------------------
__device__ float g_frames[4224*256];      // windowed STFT frames
__device__ float g_dc_h[256*144];
__device__ float g_dc_l[256*144];
__device__ float g_ds_h[256*144];
__device__ float g_ds_l[256*144];
__device__ float g_mag [128*33*129];      // [b][t][k]
__device__ int   g_topi[256];
__device__ float g_gw  [256];
__device__ float g_h1  [256*33*256];      // [pair][t][ic]
__device__ float g_eo  [256*33*256];      // [pair][t][oc]
__device__ float g_l1  [128*64*1024];
__device__ float g_h2p [128*128*256];
__device__ float g_ms2 [128*128*16];
__device__ float g_gate2[128*128];
__device__ float g_h3  [128*256*256];
__device__ float g_gate3[128*256];
__device__ float g_comb[33*128*512];
__device__ float g_ig  [33*128*1024];
__device__ float g_igb [128*1024];
__device__ float g_hbuf1[128*256];
__device__ float g_hb  [128*256];
// transposed / preconverted weights
__device__ float g_w1t  [8*645*256];
__device__ float g_w2t  [8*768*256];
__device__ unsigned g_lw2c[128*320];      // lw2 in tf32 bits
__device__ unsigned g_lw3c[256*384];      // lw3 in tf32 bits
__device__ float g_wihT [512*1024];
__device__ float g_whhT [256*1024];
__device__ float g_wihbT[512*1024];
__device__ float g_ffn1T[512*256];

__device__ __forceinline__ float sigf(float x) { return 1.0f/(1.0f+expf(-x)); }

__device__ __forceinline__ unsigned f2tf32(float x) {
    unsigned r; asm("cvt.rna.tf32.f32 %0, %1;" : "=r"(r) : "f"(x)); return r;
}
__device__ __forceinline__ void mma_tf32(float* d, const unsigned* a, const unsigned* b) {
    asm volatile(
      "mma.sync.aligned.m16n8k8.row.col.f32.tf32.tf32.f32 "
      "{%0,%1,%2,%3},{%4,%5,%6,%7},{%8,%9},{%0,%1,%2,%3};\n"
      : "+f"(d[0]), "+f"(d[1]), "+f"(d[2]), "+f"(d[3])
      : "r"(a[0]), "r"(a[1]), "r"(a[2]), "r"(a[3]), "r"(b[0]), "r"(b[1]));
}

// ------------------------- fused transposes: in[b][r][c] -> out[b][c][r] -------------------------
__global__ void k_trans_all(const float* __restrict__ p0, const float* __restrict__ p1,
                            const float* __restrict__ p4, const float* __restrict__ p5,
                            const float* __restrict__ p6, const float* __restrict__ p7) {
    int job = blockIdx.y;
    const float* in; float* out; int Bn, R, C;
    switch (job) {
        case 0: in = p0; out = g_w1t;   Bn = 8; R = 256;  C = 645; break;
        case 1: in = p1; out = g_w2t;   Bn = 8; R = 256;  C = 768; break;
        case 2: in = p4; out = g_wihT;  Bn = 1; R = 1024; C = 512; break;
        case 3: in = p5; out = g_whhT;  Bn = 1; R = 1024; C = 256; break;
        case 4: in = p6; out = g_wihbT; Bn = 1; R = 1024; C = 512; break;
        default: in = p7; out = g_ffn1T; Bn = 1; R = 256; C = 512; break;
    }
    long total = (long)Bn * R * C;
    long stride = (long)gridDim.x * blockDim.x;
    for (long i = (long)blockIdx.x*blockDim.x + threadIdx.x; i < total; i += stride) {
        long bb = i / ((long)R*C);
        long rem = i - bb*(long)R*C;
        int r = (int)(rem / C);
        int c = (int)(rem - (long)r*C);
        out[(bb*C + c)*R + r] = in[i];
    }
}

// ------------------------- pre-convert conv weights to tf32 bits -------------------------
__global__ void k_wcvt(const float* __restrict__ lw2, const float* __restrict__ lw3) {
    int i = blockIdx.x*blockDim.x + threadIdx.x;
    if (i < 128*320) g_lw2c[i] = f2tf32(lw2[i]);
    if (i < 256*384) g_lw3c[i] = f2tf32(lw3[i]);
}

// ------------------------- windowed frame builder (reflect pad, hann) -------------------------
__global__ void k_win(const float* __restrict__ xc) {
    int b = blockIdx.x, f = blockIdx.y;
    int tid = threadIdx.x;
    const float W = 6.283185307179586f/256.f;
    int p = f*128 + tid;
    int j = p - 128;
    if (j < 0) j = -j;
    else if (j >= 4096) j = 8190 - j;
    float win = 0.5f*(1.f - cosf(W*(float)tid));
    g_frames[((size_t)(b*33 + f))*256 + tid] = xc[(size_t)b*4096 + j] * win;
}

// ------------------------- DFT matrix builder -------------------------
__global__ void k_dftmat() {
    int k = blockIdx.x;
    int n = threadIdx.x;
    float c = 0.f, s = 0.f;
    if (n < 129) {
        const float W = 6.283185307179586f/256.f;
        float ang = W * (float)((k*n) & 255);
        sincosf(ang, &s, &c);
    }
    unsigned ch = f2tf32(c), sh = f2tf32(s);
    g_dc_h[k*144 + n] = __uint_as_float(ch);
    g_dc_l[k*144 + n] = c - __uint_as_float(ch);
    g_ds_h[k*144 + n] = __uint_as_float(sh);
    g_ds_l[k*144 + n] = s - __uint_as_float(sh);
}

// ------------------------- DFT magnitude via 3xTF32 MMA -------------------------
__global__ void __launch_bounds__(256) k_dft() {
    __shared__ unsigned Ah[64*20], Al[64*20];
    __shared__ unsigned Bch[16*148], Bcl[16*148];
    __shared__ unsigned Bsh[16*148], Bsl[16*148];
    int m0 = blockIdx.x * 64;
    int tid = threadIdx.x;
    int lane = tid & 31, warp = tid >> 5;
    int gid = lane >> 2, tig = lane & 3;
    int mw = (warp >> 1) * 16;
    int nbase = (warp & 1) * 72;

    float accr[9][4], acci[9][4];
    #pragma unroll
    for (int ni = 0; ni < 9; ni++)
        #pragma unroll
        for (int r = 0; r < 4; r++) { accr[ni][r] = 0.f; acci[ni][r] = 0.f; }

    for (int k0 = 0; k0 < 256; k0 += 16) {
        __syncthreads();
        #pragma unroll
        for (int j = 0; j < 4; j++) {
            int i = tid + j*256;
            int row = i >> 4, kk = i & 15;
            float x = g_frames[(size_t)(m0 + row)*256 + k0 + kk];
            unsigned h = f2tf32(x);
            Ah[row*20 + kk] = h;
            Al[row*20 + kk] = f2tf32(x - __uint_as_float(h));
        }
        #pragma unroll
        for (int j = 0; j < 9; j++) {
            int i = tid + j*256;
            if (i < 16*144) {
                int kk = i / 144, n = i - kk*144;
                size_t gidx = (size_t)(k0 + kk)*144 + n;
                Bch[kk*148 + n] = __float_as_uint(g_dc_h[gidx]);
                Bcl[kk*148 + n] = f2tf32(g_dc_l[gidx]);
                Bsh[kk*148 + n] = __float_as_uint(g_ds_h[gidx]);
                Bsl[kk*148 + n] = f2tf32(g_ds_l[gidx]);
            }
        }
        __syncthreads();
        #pragma unroll
        for (int ks = 0; ks < 2; ks++) {
            int kk0 = ks*8;
            unsigned ah[4], al[4];
            ah[0] = Ah[(mw+gid  )*20 + kk0 + tig];
            ah[1] = Ah[(mw+gid+8)*20 + kk0 + tig];
            ah[2] = Ah[(mw+gid  )*20 + kk0 + tig + 4];
            ah[3] = Ah[(mw+gid+8)*20 + kk0 + tig + 4];
            al[0] = Al[(mw+gid  )*20 + kk0 + tig];
            al[1] = Al[(mw+gid+8)*20 + kk0 + tig];
            al[2] = Al[(mw+gid  )*20 + kk0 + tig + 4];
            al[3] = Al[(mw+gid+8)*20 + kk0 + tig + 4];
            #pragma unroll
            for (int ni = 0; ni < 9; ni++) {
                int n = nbase + ni*8 + gid;
                unsigned bh[2], bl[2];
                bh[0] = Bch[(kk0+tig  )*148 + n];
                bh[1] = Bch[(kk0+tig+4)*148 + n];
                bl[0] = Bcl[(kk0+tig  )*148 + n];
                bl[1] = Bcl[(kk0+tig+4)*148 + n];
                mma_tf32(accr[ni], ah, bl);
                mma_tf32(accr[ni], al, bh);
                mma_tf32(accr[ni], ah, bh);
                bh[0] = Bsh[(kk0+tig  )*148 + n];
                bh[1] = Bsh[(kk0+tig+4)*148 + n];
                bl[0] = Bsl[(kk0+tig  )*148 + n];
                bl[1] = Bsl[(kk0+tig+4)*148 + n];
                mma_tf32(acci[ni], ah, bl);
                mma_tf32(acci[ni], al, bh);
                mma_tf32(acci[ni], ah, bh);
            }
        }
    }

    int r0 = m0 + mw + gid, r1 = r0 + 8;
    #pragma unroll
    for (int ni = 0; ni < 9; ni++) {
        int n = nbase + ni*8 + tig*2;
        if (n < 129) {
            g_mag[(size_t)r0*129 + n] = sqrtf(accr[ni][0]*accr[ni][0] + acci[ni][0]*acci[ni][0]);
            g_mag[(size_t)r1*129 + n] = sqrtf(accr[ni][2]*accr[ni][2] + acci[ni][2]*acci[ni][2]);
        }
        if (n + 1 < 129) {
            g_mag[(size_t)r0*129 + n + 1] = sqrtf(accr[ni][1]*accr[ni][1] + acci[ni][1]*acci[ni][1]);
            g_mag[(size_t)r1*129 + n + 1] = sqrtf(accr[ni][3]*accr[ni][3] + acci[ni][3]*acci[ni][3]);
        }
    }
}

// ------------------------- gating MLP + top-2 softmax -------------------------
__global__ void k_gate(const float* __restrict__ w1, const float* __restrict__ b1,
                       const float* __restrict__ w2, const float* __restrict__ b2) {
    int b = blockIdx.x;
    __shared__ float pooled[129];
    __shared__ float hid[128];
    __shared__ float lg[8];
    int tid = threadIdx.x;
    if (tid < 129) {
        float s = 0.f;
        const float* mp = g_mag + (size_t)b*33*129 + tid;
        for (int f = 0; f < 33; f++) s += mp[f*129];
        pooled[tid] = s * (1.f/33.f);
    }
    __syncthreads();
    if (tid < 128) {
        float s = b1[tid];
        const float* wr = w1 + tid*129;
        for (int i = 0; i < 129; i++) s += pooled[i]*wr[i];
        hid[tid] = fmaxf(s, 0.f);
    }
    __syncthreads();
    if (tid < 8) {
        float s = b2[tid];
        const float* wr = w2 + tid*128;
        for (int j = 0; j < 128; j++) s += hid[j]*wr[j];
        lg[tid] = s;
    }
    __syncthreads();
    if (tid == 0) {
        int i0 = 0; float v0 = lg[0];
        for (int i = 1; i < 8; i++) if (lg[i] > v0) { v0 = lg[i]; i0 = i; }
        int i1 = -1; float v1 = -3.0e38f;
        for (int i = 0; i < 8; i++) if (i != i0 && lg[i] > v1) { v1 = lg[i]; i1 = i; }
        float e = expf(v1 - v0);
        float d = 1.f/(1.f + e);
        g_topi[2*b] = i0; g_topi[2*b+1] = i1;
        g_gw[2*b] = d;    g_gw[2*b+1] = e*d;
    }
}

// ------------------------- expert conv1: SIMT fp32, vectorized LDS -------------------------
__global__ void __launch_bounds__(256) k_exp1(const float* __restrict__ eb1) {
    int pair = blockIdx.x >> 1;
    int half = blockIdx.x & 1;
    int b = pair >> 1;
    int e = g_topi[pair];
    __shared__ float ms[129][40];
    int tid = threadIdx.x;
    for (int i = tid; i < 129*40; i += 256) ((float*)ms)[i] = 0.f;
    __syncthreads();
    for (int i = tid; i < 33*129; i += 256) {
        int t = i/129, ic = i - t*129;
        ms[ic][t+2] = g_mag[(size_t)b*33*129 + i];
    }
    __syncthreads();
    int oc   = half*128 + (tid & 127);
    int tseg = tid >> 7;
    int t0   = tseg * 16;
    float acc[17];
    #pragma unroll
    for (int t = 0; t < 17; t++) acc[t] = 0.f;
    const float* wb = g_w1t + (size_t)e*645*256 + oc;
    for (int ic = 0; ic < 129; ic++) {
        float row[21];
        const float4* rp = (const float4*)&ms[ic][t0];
        #pragma unroll
        for (int j = 0; j < 5; j++) {
            float4 v = rp[j];
            row[4*j] = v.x; row[4*j+1] = v.y; row[4*j+2] = v.z; row[4*j+3] = v.w;
        }
        row[20] = ms[ic][t0 + 20];
        #pragma unroll
        for (int dk = 0; dk < 5; dk++) {
            float w = __ldg(wb + (ic*5 + dk)*256);
            #pragma unroll
            for (int t = 0; t < 17; t++) acc[t] += w * row[t+dk];
        }
    }
    float bias = eb1[e*256 + oc];
    float* op = g_h1 + (size_t)pair*33*256 + oc;
    #pragma unroll
    for (int t = 0; t < 17; t++)
        if (tseg == 0 || t > 0)
            op[(t0 + t)*256] = fmaxf(acc[t] + bias, 0.f);
}

// ------------------------- expert conv2: per-pair, vectorized, gate folded -> g_eo -----------------
__global__ void __launch_bounds__(256) k_exp2(const float* __restrict__ eb2) {
    int pair = blockIdx.x >> 1;
    int half = blockIdx.x & 1;
    int e = g_topi[pair];
    float gwk = g_gw[pair];
    __shared__ float hs[256][40];
    int tid = threadIdx.x;
    for (int i = tid; i < 256*40; i += 256) ((float*)hs)[i] = 0.f;
    __syncthreads();
    for (int i = tid; i < 33*256; i += 256) {
        int t = i >> 8, ic = i & 255;
        hs[ic][t+1] = g_h1[(size_t)pair*33*256 + i];
    }
    __syncthreads();
    int oc   = half*128 + (tid & 127);
    int tseg = tid >> 7;
    int t0   = tseg * 16;
    float acc[17];
    #pragma unroll
    for (int t = 0; t < 17; t++) acc[t] = 0.f;
    const float* wb = g_w2t + (size_t)e*768*256 + oc;
    for (int ic = 0; ic < 256; ic++) {
        float row[20];
        const float4* rp = (const float4*)&hs[ic][t0];
        #pragma unroll
        for (int j = 0; j < 5; j++) {
            float4 v = rp[j];
            row[4*j] = v.x; row[4*j+1] = v.y; row[4*j+2] = v.z; row[4*j+3] = v.w;
        }
        #pragma unroll
        for (int dk = 0; dk < 3; dk++) {
            float w = __ldg(wb + (ic*3 + dk)*256);
            #pragma unroll
            for (int t = 0; t < 17; t++) acc[t] += w * row[t+dk];
        }
    }
    float bias = eb2[e*256 + oc];
    float* op = g_eo + (size_t)pair*33*256 + oc;
    #pragma unroll
    for (int t = 0; t < 17; t++)
        if (tseg == 0 || t > 0)
            op[(t0 + t)*256] = gwk * fmaxf(acc[t] + bias, 0.f);
}

// ------------------------- line conv1 fused maxpool4 -------------------------
__global__ void __launch_bounds__(1024) k_lconv1(const float* __restrict__ xn,
                                                 const float* __restrict__ lw1,
                                                 const float* __restrict__ lb1) {
    int b = blockIdx.x;
    __shared__ float xs[4102];
    __shared__ float ws[448];
    __shared__ float bs[64];
    int tid = threadIdx.x;
    for (int i = tid; i < 4102; i += 1024) {
        int p = i - 3;
        xs[i] = (p >= 0 && p < 4096) ? xn[(size_t)b*4096 + p] : 0.f;
    }
    if (tid < 448) ws[tid] = lw1[tid];
    if (tid < 64)  bs[tid] = lb1[tid];
    __syncthreads();
    int p = tid;
    float xv[10];
    #pragma unroll
    for (int i = 0; i < 10; i++) xv[i] = xs[4*p + i];
    for (int c = 0; c < 64; c++) {
        const float* w = ws + c*7;
        float mx = -3.0e38f;
        #pragma unroll
        for (int q = 0; q < 4; q++) {
            float s = 0.f;
            #pragma unroll
            for (int k = 0; k < 7; k++) s += xv[q+k]*w[k];
            mx = fmaxf(mx, s);
        }
        g_l1[((size_t)b*64 + c)*1024 + p] = fmaxf(mx + bs[c], 0.f);
    }
}

// ------------------------- line conv2 tf32 mma (precvt weights), fused relu+pool+sums ---------------
#define LC2_SMEM ((64*133 + 128*44) * 4)
__global__ void __launch_bounds__(256) k_lconv2(const float* __restrict__ lb2) {
    extern __shared__ unsigned smu[];
    unsigned* xs = smu;                 // stride 133
    unsigned* As = smu + 64*133;        // stride 44
    int b = blockIdx.x, t0 = blockIdx.y*128;
    int tid = threadIdx.x;
    int lane = tid & 31, warp = tid >> 5;
    int gid = lane >> 2, tig = lane & 3;
    int m_base = (warp >> 1) * 32;
    int n_base = (warp & 1) * 64;

    for (int i = tid; i < 64*132; i += 256) {
        int ic = i / 132, u = i - ic*132;
        int t = t0 + u - 2;
        float v = (t >= 0 && t < 1024) ? g_l1[((size_t)b*64 + ic)*1024 + t] : 0.f;
        xs[ic*133 + u] = f2tf32(v);
    }

    float acc[2][8][4];
    #pragma unroll
    for (int mi = 0; mi < 2; mi++)
        #pragma unroll
        for (int ni = 0; ni < 8; ni++)
            #pragma unroll
            for (int r = 0; r < 4; r++) acc[mi][ni][r] = 0.f;

    for (int ic0 = 0; ic0 < 64; ic0 += 8) {
        __syncthreads();
        for (int i = tid; i < 128*40; i += 256) {
            int oc = i / 40, kk = i - oc*40;
            As[oc*44 + kk] = g_lw2c[oc*320 + ic0*5 + kk];
        }
        __syncthreads();
        #pragma unroll
        for (int ks = 0; ks < 5; ks++) {
            int kk0 = ks*8;
            unsigned a[2][4];
            #pragma unroll
            for (int mi = 0; mi < 2; mi++) {
                int row = m_base + mi*16;
                a[mi][0] = As[(row+gid  )*44 + kk0 + tig];
                a[mi][1] = As[(row+gid+8)*44 + kk0 + tig];
                a[mi][2] = As[(row+gid  )*44 + kk0 + tig + 4];
                a[mi][3] = As[(row+gid+8)*44 + kk0 + tig + 4];
            }
            int kb0 = kk0 + tig, kb1 = kb0 + 4;
            int ica = kb0/5, dka = kb0 - ica*5;
            int icb = kb1/5, dkb = kb1 - icb*5;
            const unsigned* xra = xs + (ic0 + ica)*133 + dka;
            const unsigned* xrb = xs + (ic0 + icb)*133 + dkb;
            #pragma unroll
            for (int ni = 0; ni < 8; ni++) {
                int n = n_base + ni*8 + gid;
                unsigned bfrag[2];
                bfrag[0] = xra[n];
                bfrag[1] = xrb[n];
                mma_tf32(acc[0][ni], a[0], bfrag);
                mma_tf32(acc[1][ni], a[1], bfrag);
            }
        }
    }

    int pbase = blockIdx.y*32 + (n_base >> 2);
    #pragma unroll
    for (int mi = 0; mi < 2; mi++) {
        int oc0 = m_base + mi*16 + gid, oc1 = oc0 + 8;
        float b0v = lb2[oc0], b1v = lb2[oc1];
        float s0 = 0.f, s1 = 0.f;
        #pragma unroll
        for (int ni = 0; ni < 8; ni++) {
            float v0 = fmaxf(acc[mi][ni][0] + b0v, 0.f);
            float v1 = fmaxf(acc[mi][ni][1] + b0v, 0.f);
            float v2 = fmaxf(acc[mi][ni][2] + b1v, 0.f);
            float v3 = fmaxf(acc[mi][ni][3] + b1v, 0.f);
            s0 += v0 + v1;
            s1 += v2 + v3;
            float m0 = fmaxf(v0, v1), m1 = fmaxf(v2, v3);
            m0 = fmaxf(m0, __shfl_xor_sync(0xffffffffu, m0, 1));
            m1 = fmaxf(m1, __shfl_xor_sync(0xffffffffu, m1, 1));
            if ((tig & 1) == 0) {
                int p = pbase + ni*2 + (tig >> 1);
                g_h2p[((size_t)b*128 + oc0)*256 + p] = m0;
                g_h2p[((size_t)b*128 + oc1)*256 + p] = m1;
            }
        }
        s0 += __shfl_xor_sync(0xffffffffu, s0, 1);
        s0 += __shfl_xor_sync(0xffffffffu, s0, 2);
        s1 += __shfl_xor_sync(0xffffffffu, s1, 1);
        s1 += __shfl_xor_sync(0xffffffffu, s1, 2);
        if (tig == 0) {
            int seg = blockIdx.y*2 + (warp & 1);
            g_ms2[((size_t)b*128 + oc0)*16 + seg] = s0;
            g_ms2[((size_t)b*128 + oc1)*16 + seg] = s1;
        }
    }
}

// ------------------------- SE block 2 -------------------------
__global__ void k_se2(const float* __restrict__ w1, const float* __restrict__ w2) {
    int b = blockIdx.x;
    __shared__ float mean[128];
    __shared__ float hid[32];
    int tid = threadIdx.x;
    {
        const float* mp = g_ms2 + ((size_t)b*128 + tid)*16;
        float s = 0.f;
        #pragma unroll
        for (int i = 0; i < 16; i++) s += mp[i];
        mean[tid] = s * (1.f/1024.f);
    }
    __syncthreads();
    if (tid < 32) {
        float s = 0.f;
        const float* wr = w1 + tid*128;
        for (int c = 0; c < 128; c++) s += mean[c]*wr[c];
        hid[tid] = fmaxf(s, 0.f);
    }
    __syncthreads();
    {
        float s = 0.f;
        const float* wr = w2 + tid*32;
        for (int k = 0; k < 32; k++) s += hid[k]*wr[k];
        g_gate2[b*128 + tid] = sigf(s);
    }
}

// ------------------------- line conv3 tf32 mma (precvt weights) -------------------------
#define LC3_SMEM ((128*67 + 256*28) * 4)
__global__ void __launch_bounds__(256) k_lconv3(const float* __restrict__ lb3) {
    extern __shared__ unsigned smu[];
    unsigned* xs = smu;                 // stride 67
    unsigned* As = smu + 128*67;        // stride 28
    int b = blockIdx.x, t0 = blockIdx.y*64;
    int tid = threadIdx.x;
    int lane = tid & 31, warp = tid >> 5;
    int gid = lane >> 2, tig = lane & 3;
    int m_base = (warp >> 1) * 64;
    int n_base = (warp & 1) * 32;

    for (int i = tid; i < 128*66; i += 256) {
        int ic = i / 66, u = i - ic*66;
        int t = t0 + u - 1;
        float v = 0.f;
        if (t >= 0 && t < 256)
            v = g_h2p[((size_t)b*128 + ic)*256 + t] * g_gate2[b*128 + ic];
        xs[ic*67 + u] = f2tf32(v);
    }

    float acc[4][4][4];
    #pragma unroll
    for (int mi = 0; mi < 4; mi++)
        #pragma unroll
        for (int ni = 0; ni < 4; ni++)
            #pragma unroll
            for (int r = 0; r < 4; r++) acc[mi][ni][r] = 0.f;

    for (int ic0 = 0; ic0 < 128; ic0 += 8) {
        __syncthreads();
        for (int i = tid; i < 256*24; i += 256) {
            int oc = i / 24, kk = i - oc*24;
            As[oc*28 + kk] = g_lw3c[oc*384 + ic0*3 + kk];
        }
        __syncthreads();
        #pragma unroll
        for (int ks = 0; ks < 3; ks++) {
            int kk0 = ks*8;
            unsigned a[4][4];
            #pragma unroll
            for (int mi = 0; mi < 4; mi++) {
                int row = m_base + mi*16;
                a[mi][0] = As[(row+gid  )*28 + kk0 + tig];
                a[mi][1] = As[(row+gid+8)*28 + kk0 + tig];
                a[mi][2] = As[(row+gid  )*28 + kk0 + tig + 4];
                a[mi][3] = As[(row+gid+8)*28 + kk0 + tig + 4];
            }
            int kb0 = kk0 + tig, kb1 = kb0 + 4;
            int ica = kb0/3, dka = kb0 - ica*3;
            int icb = kb1/3, dkb = kb1 - icb*3;
            const unsigned* xra = xs + (ic0 + ica)*67 + dka;
            const unsigned* xrb = xs + (ic0 + icb)*67 + dkb;
            #pragma unroll
            for (int ni = 0; ni < 4; ni++) {
                int n = n_base + ni*8 + gid;
                unsigned bfrag[2];
                bfrag[0] = xra[n];
                bfrag[1] = xrb[n];
                #pragma unroll
                for (int mi = 0; mi < 4; mi++)
                    mma_tf32(acc[mi][ni], a[mi], bfrag);
            }
        }
    }

    #pragma unroll
    for (int mi = 0; mi < 4; mi++) {
        int oc0 = m_base + mi*16 + gid, oc1 = oc0 + 8;
        float b0v = lb3[oc0], b1v = lb3[oc1];
        float* p0b = g_h3 + ((size_t)b*256 + oc0)*256 + t0;
        float* p1b = g_h3 + ((size_t)b*256 + oc1)*256 + t0;
        #pragma unroll
        for (int ni = 0; ni < 4; ni++) {
            int t = n_base + ni*8 + tig*2;
            p0b[t  ] = fmaxf(acc[mi][ni][0] + b0v, 0.f);
            p0b[t+1] = fmaxf(acc[mi][ni][1] + b0v, 0.f);
            p1b[t  ] = fmaxf(acc[mi][ni][2] + b1v, 0.f);
            p1b[t+1] = fmaxf(acc[mi][ni][3] + b1v, 0.f);
        }
    }
}

// ------------------------- SE block 3 -------------------------
__global__ void k_se3(const float* __restrict__ w1, const float* __restrict__ w2) {
    int b = blockIdx.x;
    __shared__ float mean[256];
    __shared__ float hid[64];
    int tid = threadIdx.x;
    {
        const float4* p = (const float4*)(g_h3 + ((size_t)b*256 + tid)*256);
        float s = 0.f;
        for (int i = 0; i < 64; i++) { float4 v = p[i]; s += v.x+v.y+v.z+v.w; }
        mean[tid] = s * (1.f/256.f);
    }
    __syncthreads();
    if (tid < 64) {
        float s = 0.f;
        const float* wr = w1 + tid*256;
        for (int c = 0; c < 256; c++) s += mean[c]*wr[c];
        hid[tid] = fmaxf(s, 0.f);
    }
    __syncthreads();
    {
        float s = 0.f;
        const float* wr = w2 + tid*64;
        for (int k = 0; k < 64; k++) s += hid[k]*wr[k];
        g_gate3[b*256 + tid] = sigf(s);
    }
}

// ------------------------- build comb[t][b][c] -------------------------
__global__ void k_comb() {
    const float scale = 64.f/33.f;
    int total = 33*128*512;
    for (int idx = blockIdx.x*blockDim.x + threadIdx.x; idx < total;
         idx += gridDim.x*blockDim.x) {
        int c = idx & 511;
        int rem = idx >> 9;
        int b = rem & 127;
        int t = rem >> 7;
        float v;
        if (c < 256) {
            v = g_eo[((size_t)(b*2    )*33 + t)*256 + c]
              + g_eo[((size_t)(b*2 + 1)*33 + t)*256 + c];
        } else {
            int cc = c - 256;
            float co = ((float)t + 0.5f)*scale - 0.5f;
            co = fminf(fmaxf(co, 0.f), 63.f);
            int lo = (int)floorf(co);
            int hi = min(lo + 1, 63);
            float w = co - (float)lo;
            const float* hp = g_h3 + ((size_t)b*256 + cc)*256;
            float g = g_gate3[b*256 + cc];
            const float* pl = hp + 4*lo;
            float vl = fmaxf(fmaxf(pl[0], pl[1]), fmaxf(pl[2], pl[3]));
            const float* ph = hp + 4*hi;
            float vh = fmaxf(fmaxf(ph[0], ph[1]), fmaxf(ph[2], ph[3]));
            v = g * (vl*(1.f - w) + vh*w);
        }
        g_comb[idx] = v;
    }
}

// ------------------------- GEMM via 3xTF32 mma (error-compensated) -------------------------
#define GEMM_SMEM ((128*36 + 32*132) * 8)
__global__ void __launch_bounds__(256) k_gemm(int mode,
        const float* __restrict__ bi1, const float* __restrict__ bi2) {
    extern __shared__ unsigned smu[];
    unsigned* Ash = smu;
    unsigned* Asl = smu + 128*36;
    unsigned* Bsh = smu + 2*128*36;
    unsigned* Bsl = smu + 2*128*36 + 32*132;
    const float* A; const float* Bt; float* C;
    if (mode == 0) { A = g_comb;              Bt = g_wihT;  C = g_ig;  }
    else           { A = g_comb + 32*128*512; Bt = g_wihbT; C = g_igb; }
    int m0 = blockIdx.x*128, n0 = blockIdx.y*128;
    int tid = threadIdx.x;
    int lane = tid & 31, warp = tid >> 5;
    int gid = lane >> 2, tig = lane & 3;
    int m_base = (warp >> 1) * 32;
    int n_base = (warp & 1) * 64;

    float acc[2][8][4];
    #pragma unroll
    for (int mi = 0; mi < 2; mi++)
        #pragma unroll
        for (int ni = 0; ni < 8; ni++)
            #pragma unroll
            for (int r = 0; r < 4; r++) acc[mi][ni][r] = 0.f;

    for (int k0 = 0; k0 < 512; k0 += 32) {
        __syncthreads();
        #pragma unroll
        for (int j = 0; j < 16; j++) {
            int i = tid + j*256;
            int row = i >> 5, kk = i & 31;
            float x = A[(size_t)(m0+row)*512 + k0 + kk];
            unsigned h = f2tf32(x);
            Ash[row*36 + kk] = h;
            Asl[row*36 + kk] = f2tf32(x - __uint_as_float(h));
        }
        #pragma unroll
        for (int j = 0; j < 16; j++) {
            int i = tid + j*256;
            int kk = i >> 7, n = i & 127;
            float x = Bt[(size_t)(k0+kk)*1024 + n0 + n];
            unsigned h = f2tf32(x);
            Bsh[kk*132 + n] = h;
            Bsl[kk*132 + n] = f2tf32(x - __uint_as_float(h));
        }
        __syncthreads();
        #pragma unroll
        for (int ks = 0; ks < 4; ks++) {
            int kk0 = ks*8;
            unsigned ah[2][4], al[2][4];
            #pragma unroll
            for (int mi = 0; mi < 2; mi++) {
                int row = m_base + mi*16;
                ah[mi][0] = Ash[(row+gid  )*36 + kk0 + tig];
                ah[mi][1] = Ash[(row+gid+8)*36 + kk0 + tig];
                ah[mi][2] = Ash[(row+gid  )*36 + kk0 + tig + 4];
                ah[mi][3] = Ash[(row+gid+8)*36 + kk0 + tig + 4];
                al[mi][0] = Asl[(row+gid  )*36 + kk0 + tig];
                al[mi][1] = Asl[(row+gid+8)*36 + kk0 + tig];
                al[mi][2] = Asl[(row+gid  )*36 + kk0 + tig + 4];
                al[mi][3] = Asl[(row+gid+8)*36 + kk0 + tig + 4];
            }
            #pragma unroll
            for (int ni = 0; ni < 8; ni++) {
                int n = n_base + ni*8 + gid;
                unsigned bh[2], bl[2];
                bh[0] = Bsh[(kk0+tig  )*132 + n];
                bh[1] = Bsh[(kk0+tig+4)*132 + n];
                bl[0] = Bsl[(kk0+tig  )*132 + n];
                bl[1] = Bsl[(kk0+tig+4)*132 + n];
                mma_tf32(acc[0][ni], ah[0], bl);
                mma_tf32(acc[0][ni], al[0], bh);
                mma_tf32(acc[0][ni], ah[0], bh);
                mma_tf32(acc[1][ni], ah[1], bl);
                mma_tf32(acc[1][ni], al[1], bh);
                mma_tf32(acc[1][ni], ah[1], bh);
            }
        }
    }

    #pragma unroll
    for (int mi = 0; mi < 2; mi++) {
        int m0r = m0 + m_base + mi*16 + gid;
        int m1r = m0r + 8;
        #pragma unroll
        for (int ni = 0; ni < 8; ni++) {
            int n = n0 + n_base + ni*8 + tig*2;
            float bb0 = bi1[n] + bi2[n], bb1 = bi1[n+1] + bi2[n+1];
            C[(size_t)m0r*1024 + n    ] = acc[mi][ni][0] + bb0;
            C[(size_t)m0r*1024 + n + 1] = acc[mi][ni][1] + bb1;
            C[(size_t)m1r*1024 + n    ] = acc[mi][ni][2] + bb0;
            C[(size_t)m1r*1024 + n + 1] = acc[mi][ni][3] + bb1;
        }
    }
}

// ------------------------- persistent cluster LSTM -------------------------
#define LSTM_SMEM ((256*128 + 2*8*256 + 8*8*128) * 4)
__global__ void __cluster_dims__(8,1,1) __launch_bounds__(256, 1) k_lstm() {
    extern __shared__ float sm[];
    float* ws   = sm;
    float* hbuf = sm + 256*128;
    float* red  = hbuf + 2*8*256;
    int tid = threadIdx.x;
    unsigned rank;
    asm("mov.u32 %0, %%cluster_ctarank;" : "=r"(rank));
    int bg = blockIdx.x >> 3;
    int j0 = (int)rank * 32;

    for (int i = tid; i < 256*128; i += 256) {
        int k = i >> 7; int col = i & 127;
        int g = col >> 5; int jj = col & 31;
        ws[i] = g_whhT[k*1024 + g*256 + j0 + jj];
    }
    for (int i = tid; i < 8*256; i += 256) hbuf[i] = 0.f;
    __syncthreads();
    asm volatile("barrier.cluster.arrive.aligned;" ::: "memory");
    asm volatile("barrier.cluster.wait.aligned;" ::: "memory");

    int ks = tid >> 5, jj = tid & 31;
    int rb = tid >> 5, rjj = tid & 31;
    float c_reg = 0.f;
    float hval  = 0.f;

    for (int t = 0; t < 33; t++) {
        const float* hp = hbuf + (t & 1) * 2048;
        float acc[8][4];
        #pragma unroll
        for (int b = 0; b < 8; b++)
            #pragma unroll
            for (int g = 0; g < 4; g++) acc[b][g] = 0.f;
        int kbase = ks*32;
        #pragma unroll 4
        for (int kk = 0; kk < 32; kk++) {
            int k = kbase + kk;
            float w0 = ws[k*128 + jj];
            float w1 = ws[k*128 + 32 + jj];
            float w2 = ws[k*128 + 64 + jj];
            float w3 = ws[k*128 + 96 + jj];
            #pragma unroll
            for (int b = 0; b < 8; b++) {
                float hk = hp[b*256 + k];
                acc[b][0] += hk*w0; acc[b][1] += hk*w1;
                acc[b][2] += hk*w2; acc[b][3] += hk*w3;
            }
        }
        #pragma unroll
        for (int b = 0; b < 8; b++)
            #pragma unroll
            for (int g = 0; g < 4; g++)
                red[(ks*8 + b)*128 + g*32 + jj] = acc[b][g];
        __syncthreads();

        float gi = 0.f, gf = 0.f, gg = 0.f, go = 0.f;
        #pragma unroll
        for (int q = 0; q < 8; q++) {
            const float* rp = red + (q*8 + rb)*128;
            gi += rp[rjj]; gf += rp[32+rjj]; gg += rp[64+rjj]; go += rp[96+rjj];
        }
        const float* igp = g_ig + ((size_t)t*128 + bg*8 + rb)*1024 + j0 + rjj;
        gi += igp[0]; gf += igp[256]; gg += igp[512]; go += igp[768];
        c_reg = sigf(gf)*c_reg + sigf(gi)*tanhf(gg);
        hval  = sigf(go)*tanhf(c_reg);

        uint32_t dst_local = (uint32_t)__cvta_generic_to_shared(
            hbuf + ((t+1)&1)*2048 + rb*256 + j0 + rjj);
        #pragma unroll
        for (int r = 0; r < 8; r++) {
            uint32_t remote;
            asm volatile("mapa.shared::cluster.u32 %0, %1, %2;"
                         : "=r"(remote) : "r"(dst_local), "r"(r));
            asm volatile("st.shared::cluster.f32 [%0], %1;"
                         :: "r"(remote), "f"(hval) : "memory");
        }
        asm volatile("barrier.cluster.arrive.aligned;" ::: "memory");
        asm volatile("barrier.cluster.wait.aligned;" ::: "memory");
    }
    g_hbuf1[(bg*8 + rb)*256 + j0 + rjj] = hval;
}

// ------------------------- backward LSTM: single step from zero state -------------------------
__global__ void k_bw() {
    int idx = blockIdx.x*blockDim.x + threadIdx.x;
    if (idx >= 128*256) return;
    int b = idx >> 8, j = idx & 255;
    const float* gp = g_igb + b*1024;
    float gi = gp[j], gg = gp[512+j], go = gp[768+j];
    float c = sigf(gi)*tanhf(gg);
    g_hb[idx] = sigf(go)*tanhf(c);
}

// ------------------------- final FFN -------------------------
__global__ void k_ffn(const float* __restrict__ b1v, const float* __restrict__ w2,
                      const float* __restrict__ b2v, float* __restrict__ out) {
    int b = blockIdx.x;
    __shared__ float last[512];
    __shared__ float red[256];
    int tid = threadIdx.x;
    last[tid]       = g_hbuf1[b*256 + tid];
    last[256 + tid] = g_hb[b*256 + tid];
    __syncthreads();
    float s = b1v[tid];
    for (int k = 0; k < 512; k++) s += last[k]*g_ffn1T[k*256 + tid];
    s = fmaxf(s, 0.f);
    red[tid] = s * w2[tid];
    __syncthreads();
    for (int off = 128; off > 0; off >>= 1) {
        if (tid < off) red[tid] += red[tid + off];
        __syncthreads();
    }
    if (tid == 0) out[b] = red[0] + b2v[0];
}

// ------------------------- launch -------------------------
extern "C" void kernel_launch(void* const* d_in, const int* in_sizes, int n_in,
                              void* d_out, int out_size) {
    const float* x_continuum  = (const float*)d_in[0];
    const float* x_normalized = (const float*)d_in[1];
    const float* gate_w1 = (const float*)d_in[2];
    const float* gate_b1 = (const float*)d_in[3];
    const float* gate_w2 = (const float*)d_in[4];
    const float* gate_b2 = (const float*)d_in[5];
    const float* exp_w1  = (const float*)d_in[6];
    const float* exp_b1  = (const float*)d_in[7];
    const float* exp_w2  = (const float*)d_in[8];
    const float* exp_b2  = (const float*)d_in[9];
    const float* lw1 = (const float*)d_in[10];
    const float* lb1 = (const float*)d_in[11];
    const float* lw2 = (const float*)d_in[12];
    const float* lb2 = (const float*)d_in[13];
    const float* se2_w1 = (const float*)d_in[14];
    const float* se2_w2 = (const float*)d_in[15];
    const float* lw3 = (const float*)d_in[16];
    const float* lb3 = (const float*)d_in[17];
    const float* se3_w1 = (const float*)d_in[18];
    const float* se3_w2 = (const float*)d_in[19];
    const float* wih_f = (const float*)d_in[20];
    const float* whh_f = (const float*)d_in[21];
    const float* bih_f = (const float*)d_in[22];
    const float* bhh_f = (const float*)d_in[23];
    const float* wih_b = (const float*)d_in[24];
    // d_in[25] = whh_b: unused (backward LSTM only contributes one step from h=0)
    const float* bih_b = (const float*)d_in[26];
    const float* bhh_b = (const float*)d_in[27];
    const float* ffn_w1 = (const float*)d_in[28];
    const float* ffn_b1 = (const float*)d_in[29];
    const float* ffn_w2 = (const float*)d_in[30];
    const float* ffn_b2 = (const float*)d_in[31];
    float* out = (float*)d_out;

    static bool s_init = false;
    static cudaStream_t s1, s2;
    static cudaEvent_t eF, eT, eJ1, eC, eJ3, eEnd;
    if (!s_init) {
        cudaStreamCreateWithFlags(&s1, cudaStreamNonBlocking);
        cudaStreamCreateWithFlags(&s2, cudaStreamNonBlocking);
        cudaEventCreateWithFlags(&eF,   cudaEventDisableTiming);
        cudaEventCreateWithFlags(&eT,   cudaEventDisableTiming);
        cudaEventCreateWithFlags(&eJ1,  cudaEventDisableTiming);
        cudaEventCreateWithFlags(&eC,   cudaEventDisableTiming);
        cudaEventCreateWithFlags(&eJ3,  cudaEventDisableTiming);
        cudaEventCreateWithFlags(&eEnd, cudaEventDisableTiming);
        cudaFuncSetAttribute(k_lstm,   cudaFuncAttributeMaxDynamicSharedMemorySize, LSTM_SMEM);
        cudaFuncSetAttribute(k_lconv2, cudaFuncAttributeMaxDynamicSharedMemorySize, LC2_SMEM);
        cudaFuncSetAttribute(k_lconv3, cudaFuncAttributeMaxDynamicSharedMemorySize, LC3_SMEM);
        cudaFuncSetAttribute(k_gemm,   cudaFuncAttributeMaxDynamicSharedMemorySize, GEMM_SMEM);
        s_init = true;
    }

    // fork from capture stream
    cudaEventRecord(eF, 0);
    cudaStreamWaitEvent(s1, eF, 0);
    cudaStreamWaitEvent(s2, eF, 0);

    // s2: weight prep + line branch (lconv2 4th for ncu)
    k_trans_all<<<dim3(768, 6), 256, 0, s2>>>(exp_w1, exp_w2, wih_f, whh_f, wih_b, ffn_w1);   // 1
    cudaEventRecord(eT, s2);
    k_wcvt<<<384, 256, 0, s2>>>(lw2, lw3);                                                     // 2
    k_lconv1<<<128, 1024, 0, s2>>>(x_normalized, lw1, lb1);                                    // 3
    k_lconv2<<<dim3(128, 8), 256, LC2_SMEM, s2>>>(lb2);                                        // 4
    k_dftmat<<<256, 144, 0, s1>>>();
    k_win<<<dim3(128, 33), 256, 0, s1>>>(x_continuum);
    k_dft<<<66, 256, 0, s1>>>();
    k_gate<<<128, 160, 0, s1>>>(gate_w1, gate_b1, gate_w2, gate_b2);
    k_se2<<<128, 128, 0, s2>>>(se2_w1, se2_w2);
    k_lconv3<<<dim3(128, 4), 256, LC3_SMEM, s2>>>(lb3);
    k_se3<<<128, 256, 0, s2>>>(se3_w1, se3_w2);

    cudaStreamWaitEvent(s1, eT, 0);          // experts need transposed weights
    k_exp1<<<512, 256, 0, s1>>>(exp_b1);
    k_exp2<<<512, 256, 0, s1>>>(exp_b2);
    cudaEventRecord(eJ1, s1);

    // s2: join freq, build comb
    cudaStreamWaitEvent(s2, eJ1, 0);
    k_comb<<<2048, 512, 0, s2>>>();
    cudaEventRecord(eC, s2);

    // s1: backward-LSTM path overlaps forward GEMM
    cudaStreamWaitEvent(s1, eC, 0);
    k_gemm<<<dim3(1, 8), 256, GEMM_SMEM, s1>>>(1, bih_b, bhh_b);
    k_bw<<<128, 256, 0, s1>>>();
    cudaEventRecord(eJ3, s1);

    // s2: forward input projections + persistent LSTM + FFN
    k_gemm<<<dim3(33, 8), 256, GEMM_SMEM, s2>>>(0, bih_f, bhh_f);
    k_lstm<<<128, 256, LSTM_SMEM, s2>>>();
    cudaStreamWaitEvent(s2, eJ3, 0);
    k_ffn<<<128, 256, 0, s2>>>(ffn_b1, ffn_w2, ffn_b2, out);
    cudaEventRecord(eEnd, s2);

    // join back to capture stream
    cudaStreamWaitEvent(0, eEnd, 0);
}